// round 10
// baseline (speedup 1.0000x reference)
#include <cuda_runtime.h>
#include <cuda_bf16.h>
#include <cstdint>

// Problem constants
#define DIM    256
#define NEMB   8192
#define NROWS  16384            // 16*32*32
#define DECAYF 0.99f
#define OMDEC  0.01f
#define EPSF   1e-5f
#define SCALE  20.0f
#define INVS2  (1.0f / (SCALE * SCALE))
#define MARGIN 3.0f
#define THRC   2.4f
#define CCAP   32               // candidates per (row, slot)
#define NSLOT  16               // slots per row (4 nwarp x 4 lane%4)

// Output layout (flattened concatenation of reference return tuple, all fp32)
#define OFF_Q    0ul
#define OFF_DIFF 4194304ul
#define OFF_IND  4194305ul
#define OFF_NE   4210689ul
#define OFF_NCS  6307841ul
#define OFF_NEA  6316033ul

// ---------------------------------------------------------------------------
// Device scratch
// ---------------------------------------------------------------------------
__device__ float    g_Et[(size_t)NEMB * DIM];       // embedding transposed fp32
__device__ int8_t   g_E8[(size_t)NEMB * DIM];       // embedding transposed int8
__device__ int8_t   g_A8[(size_t)NROWS * DIM];      // z rows int8
__device__ float    g_halfnorm[NEMB];               // 0.5*||e||^2 fp32
__device__ int2     g_cand[(size_t)NROWS * NSLOT * CCAP];  // {code, score bits}
__device__ int      g_ccnt[(size_t)NROWS * NSLOT];
__device__ int      g_ind[NROWS];
__device__ float    g_embed_sum[(size_t)DIM * NEMB];
__device__ float    g_onehot[NEMB];
__device__ float    g_scal[2];                      // [0]=diff_sum, [1]=n_sum

// ---------------------------------------------------------------------------
// PTX helpers — base-target instructions only (cp.async / ldmatrix / mma.sync)
// ---------------------------------------------------------------------------
__device__ __forceinline__ uint32_t smem_u32(const void* p) {
    uint32_t a;
    asm("{ .reg .u64 t; cvta.to.shared.u64 t, %1; cvt.u32.u64 %0, t; }" : "=r"(a) : "l"(p));
    return a;
}
#define SW128(x) ((x) ^ (((x) >> 3) & 0x70))
#define CP_ASYNC16(dst, src) \
    asm volatile("cp.async.cg.shared.global [%0], [%1], 16;" :: "r"(dst), "l"(src) : "memory")
#define CP_COMMIT() asm volatile("cp.async.commit_group;" ::: "memory")
#define CP_WAIT0()  asm volatile("cp.async.wait_group 0;" ::: "memory")
#define CP_WAIT1()  asm volatile("cp.async.wait_group 1;" ::: "memory")

#define LDSM4(r, addr) \
    asm volatile("ldmatrix.sync.aligned.m8n8.x4.shared.b16 {%0,%1,%2,%3}, [%4];" \
        : "=r"((r)[0]), "=r"((r)[1]), "=r"((r)[2]), "=r"((r)[3]) : "r"(addr))

#define IMMA16832(c, a, b0, b1) \
    asm volatile("mma.sync.aligned.m16n8k32.row.col.s32.s8.s8.s32 " \
        "{%0,%1,%2,%3}, {%4,%5,%6,%7}, {%8,%9}, {%0,%1,%2,%3};" \
        : "+r"((c)[0]), "+r"((c)[1]), "+r"((c)[2]), "+r"((c)[3]) \
        : "r"((a)[0]), "r"((a)[1]), "r"((a)[2]), "r"((a)[3]), "r"(b0), "r"(b1))

__device__ __forceinline__ int q8(float x) {
    float v = fminf(fmaxf(x * SCALE, -127.0f), 127.0f);
    return __float2int_rn(v);
}

// ---------------------------------------------------------------------------
// Zero the accumulators
// ---------------------------------------------------------------------------
__global__ void zero_kernel() {
    int i = blockIdx.x * blockDim.x + threadIdx.x;
    int stride = gridDim.x * blockDim.x;
    for (size_t k = i; k < (size_t)DIM * NEMB; k += stride) g_embed_sum[k] = 0.0f;
    if (i < NEMB) g_onehot[i] = 0.0f;
    if (i < 2)    g_scal[i]   = 0.0f;
}

// ---------------------------------------------------------------------------
// Transpose embedding [DIM, NEMB] -> Et [NEMB, DIM] fp32 + int8
// ---------------------------------------------------------------------------
__global__ void transpose_kernel(const float* __restrict__ E) {
    __shared__ float tile[32][33];
    int jx = blockIdx.x * 32;
    int dy = blockIdx.y * 32;
    int tx = threadIdx.x;
    #pragma unroll
    for (int r = threadIdx.y; r < 32; r += 8)
        tile[r][tx] = E[(size_t)(dy + r) * NEMB + jx + tx];
    __syncthreads();
    #pragma unroll
    for (int r = threadIdx.y; r < 32; r += 8) {
        float v = tile[tx][r];
        size_t o = (size_t)(jx + r) * DIM + dy + tx;
        g_Et[o] = v;
        g_E8[o] = (int8_t)q8(v);
    }
}

// ---------------------------------------------------------------------------
// z -> int8
// ---------------------------------------------------------------------------
__global__ void convz_kernel(const float* __restrict__ z) {
    size_t i = (size_t)blockIdx.x * blockDim.x + threadIdx.x;   // one float4
    float4 v = ((const float4*)z)[i];
    uint32_t p = (uint32_t)(q8(v.x) & 255)
               | ((uint32_t)(q8(v.y) & 255) << 8)
               | ((uint32_t)(q8(v.z) & 255) << 16)
               | ((uint32_t)(q8(v.w) & 255) << 24);
    ((uint32_t*)g_A8)[i] = p;
}

// ---------------------------------------------------------------------------
// halfnorm from Et (deterministic)
// ---------------------------------------------------------------------------
__global__ void norm_kernel() {
    int w    = threadIdx.x >> 5;
    int lane = threadIdx.x & 31;
    int j = blockIdx.x * 8 + w;
    const float4* e4 = (const float4*)(g_Et + (size_t)j * DIM);
    float s = 0.0f;
    float4 v = e4[lane];
    s += v.x * v.x + v.y * v.y + v.z * v.z + v.w * v.w;
    v = e4[lane + 32];
    s += v.x * v.x + v.y * v.y + v.z * v.z + v.w * v.w;
    #pragma unroll
    for (int off = 16; off; off >>= 1) s += __shfl_down_sync(0xffffffffu, s, off);
    if (lane == 0) g_halfnorm[j] = 0.5f * s;
}

// ---------------------------------------------------------------------------
// INT8 IMMA distance GEMM + margin-candidate argmax (score-carrying).
// Grid 256 (M-tile 64). 8 warps: mwarp = wid&1 (32 rows), nwarp = wid>>1 (32 codes).
// K = 256 bytes as 2 chunks of [rows x 128B], SW128. B: 3-stage cp.async pipeline.
// ---------------------------------------------------------------------------
#define SMEM_A      0
#define SMEM_B      16384       // 3 buffers of 32KB
#define SMEM_TOTAL  114688

__global__ void __launch_bounds__(256, 2)
imma_argmax_kernel() {
    extern __shared__ __align__(1024) char smem[];
    uint32_t sb = smem_u32(smem);
    const int tid = threadIdx.x, wid = tid >> 5, lane = tid & 31;
    const int mwarp = wid & 1, nwarp = wid >> 1;
    const int m0 = blockIdx.x * 64;

    // ---- prologue: A tile (group0) + B0 (group0) + B1 (group1) ----
    {
        const int8_t* Arow = g_A8 + (size_t)m0 * DIM;
        for (int u = tid; u < 1024; u += 256) {
            int chunk = u >> 9, rem = u & 511, row = rem >> 3, seg = rem & 7;
            uint32_t dst = sb + SMEM_A + chunk * 8192 + SW128(row * 128 + seg * 16);
            CP_ASYNC16(dst, Arow + (size_t)row * DIM + chunk * 128 + seg * 16);
        }
        for (int u = tid; u < 2048; u += 256) {
            int chunk = u >> 10, rem = u & 1023, row = rem >> 3, seg = rem & 7;
            uint32_t dst = sb + SMEM_B + chunk * 16384 + SW128(row * 128 + seg * 16);
            CP_ASYNC16(dst, g_E8 + (size_t)row * DIM + chunk * 128 + seg * 16);
        }
        CP_COMMIT();
        for (int u = tid; u < 2048; u += 256) {
            int chunk = u >> 10, rem = u & 1023, row = rem >> 3, seg = rem & 7;
            uint32_t dst = sb + SMEM_B + 32768 + chunk * 16384 + SW128(row * 128 + seg * 16);
            CP_ASYNC16(dst, g_E8 + (size_t)(128 + row) * DIM + chunk * 128 + seg * 16);
        }
        CP_COMMIT();
        CP_WAIT1();           // A + B0 resident
    }
    __syncthreads();

    // per-thread row ownership (c-frag): rows q, q+8 per m16 tile; 2 m-tiles
    const int q = lane >> 2;
    int rowIdx[4];
    rowIdx[0] = m0 + mwarp * 32 + q;        // m=0, +0
    rowIdx[1] = rowIdx[0] + 8;              // m=0, +8
    rowIdx[2] = rowIdx[0] + 16;             // m=1, +0
    rowIdx[3] = rowIdx[0] + 24;             // m=1, +8
    const int slot = nwarp * 4 + (lane & 3);
    const int colb = (lane & 3) * 2;
    const int alr  = lane & 15;
    const int kseg16 = (lane >> 4) * 16;

    float best[4] = {-3.0e38f, -3.0e38f, -3.0e38f, -3.0e38f};
    int   cnt[4]  = {0, 0, 0, 0};

    for (int t = 0; t < 64; t++) {
        const uint32_t bbase = sb + SMEM_B + (t % 3) * 32768;

        // prefetch tile t+2 into buffer (t+2)%3 (freed after iteration t-1)
        if (t + 2 < 64) {
            uint32_t nb = sb + SMEM_B + ((t + 2) % 3) * 32768;
            const int8_t* Brow = g_E8 + (size_t)(t + 2) * 128 * DIM;
            for (int u = tid; u < 2048; u += 256) {
                int chunk = u >> 10, rem = u & 1023, row = rem >> 3, seg = rem & 7;
                CP_ASYNC16(nb + chunk * 16384 + SW128(row * 128 + seg * 16),
                           Brow + (size_t)row * DIM + chunk * 128 + seg * 16);
            }
            CP_COMMIT();
        }

        int acc[2][4][4];
        #pragma unroll
        for (int m = 0; m < 2; m++)
            #pragma unroll
            for (int j = 0; j < 4; j++)
                #pragma unroll
                for (int r = 0; r < 4; r++) acc[m][j][r] = 0;

        #pragma unroll
        for (int ks = 0; ks < 8; ks++) {
            const int chunk = ks >> 2;
            const int koff = (ks & 3) * 32 + kseg16;

            uint32_t aF[2][4];
            LDSM4(aF[0], sb + SMEM_A + chunk * 8192
                         + SW128((mwarp * 32 + alr) * 128 + koff));
            LDSM4(aF[1], sb + SMEM_A + chunk * 8192
                         + SW128((mwarp * 32 + 16 + alr) * 128 + koff));

            uint32_t bF[2][4];
            #pragma unroll
            for (int p = 0; p < 2; p++)
                LDSM4(bF[p], bbase + chunk * 16384
                             + SW128((nwarp * 32 + p * 16 + alr) * 128 + koff));

            #pragma unroll
            for (int m = 0; m < 2; m++)
                #pragma unroll
                for (int p = 0; p < 2; p++) {
                    IMMA16832(acc[m][2 * p],     aF[m], bF[p][0], bF[p][2]);
                    IMMA16832(acc[m][2 * p + 1], aF[m], bF[p][1], bF[p][3]);
                }
        }

        // ---- epilogue: scores -> margin candidates with carried approx score ----
        const int n0 = t * 128 + nwarp * 32;
        #pragma unroll
        for (int j = 0; j < 4; j++) {
            const int c0 = n0 + j * 8 + colb;
            const float hn0 = __ldg(&g_halfnorm[c0]);
            const float hn1 = __ldg(&g_halfnorm[c0 + 1]);
            #pragma unroll
            for (int m = 0; m < 2; m++) {
                float s00 = __int2float_rn(acc[m][j][0]) * INVS2 - hn0;
                float s01 = __int2float_rn(acc[m][j][1]) * INVS2 - hn1;
                float s10 = __int2float_rn(acc[m][j][2]) * INVS2 - hn0;
                float s11 = __int2float_rn(acc[m][j][3]) * INVS2 - hn1;
                const int r0 = m * 2, r1 = m * 2 + 1;
                if (s00 > best[r0] - MARGIN) {
                    if (cnt[r0] < CCAP)
                        g_cand[((size_t)rowIdx[r0] * NSLOT + slot) * CCAP + cnt[r0]]
                            = make_int2(c0, __float_as_int(s00));
                    cnt[r0]++; if (s00 > best[r0]) best[r0] = s00;
                }
                if (s01 > best[r0] - MARGIN) {
                    if (cnt[r0] < CCAP)
                        g_cand[((size_t)rowIdx[r0] * NSLOT + slot) * CCAP + cnt[r0]]
                            = make_int2(c0 + 1, __float_as_int(s01));
                    cnt[r0]++; if (s01 > best[r0]) best[r0] = s01;
                }
                if (s10 > best[r1] - MARGIN) {
                    if (cnt[r1] < CCAP)
                        g_cand[((size_t)rowIdx[r1] * NSLOT + slot) * CCAP + cnt[r1]]
                            = make_int2(c0, __float_as_int(s10));
                    cnt[r1]++; if (s10 > best[r1]) best[r1] = s10;
                }
                if (s11 > best[r1] - MARGIN) {
                    if (cnt[r1] < CCAP)
                        g_cand[((size_t)rowIdx[r1] * NSLOT + slot) * CCAP + cnt[r1]]
                            = make_int2(c0 + 1, __float_as_int(s11));
                    cnt[r1]++; if (s11 > best[r1]) best[r1] = s11;
                }
            }
        }

        if (t + 1 < 64) { if (t + 2 < 64) CP_WAIT1(); else CP_WAIT0(); }
        __syncthreads();
    }

    #pragma unroll
    for (int r = 0; r < 4; r++)
        g_ccnt[(size_t)rowIdx[r] * NSLOT + slot] = cnt[r];
}

// ---------------------------------------------------------------------------
// Contender-only fp32 rescore. One warp per row.
//  1) approx max over all stored candidate scores
//  2) exact fp32 warp-dot only for candidates within THRC of approx max
//  3) slots that overflowed CCAP: exact-scan their 512-code range
// ---------------------------------------------------------------------------
__global__ void rescore_kernel(const float* __restrict__ z) {
    __shared__ int cbuf[8][96];
    int w = threadIdx.x >> 5, lane = threadIdx.x & 31;
    int row = blockIdx.x * 8 + w;
    const float4* zr = (const float4*)(z + (size_t)row * DIM);
    float4 z0 = zr[lane], z1 = zr[lane + 32];

    int cnt_s = (lane < NSLOT) ? g_ccnt[(size_t)row * NSLOT + lane] : 0;
    unsigned ovf = __ballot_sync(0xffffffffu, lane < NSLOT && cnt_s > CCAP);

    // phase 1: approx max over stored scores
    float am = -3.0e38f;
    for (int s = 0; s < NSLOT; s++) {
        int n = min(__shfl_sync(0xffffffffu, cnt_s, s), CCAP);
        const int2* lst = g_cand + ((size_t)row * NSLOT + s) * CCAP;
        for (int e = lane; e < n; e += 32)
            am = fmaxf(am, __int_as_float(lst[e].y));
    }
    #pragma unroll
    for (int off = 16; off; off >>= 1)
        am = fmaxf(am, __shfl_xor_sync(0xffffffffu, am, off));

    // phase 2: gather contenders
    int cc = 0;
    for (int s = 0; s < NSLOT; s++) {
        int n = min(__shfl_sync(0xffffffffu, cnt_s, s), CCAP);
        const int2* lst = g_cand + ((size_t)row * NSLOT + s) * CCAP;
        for (int base = 0; base < n; base += 32) {
            int e = base + lane;
            bool hit = false; int code = 0;
            if (e < n) {
                int2 v = lst[e];
                if (__int_as_float(v.y) >= am - THRC) { hit = true; code = v.x; }
            }
            unsigned msk = __ballot_sync(0xffffffffu, hit);
            if (hit) {
                int pos = cc + __popc(msk & ((1u << lane) - 1u));
                if (pos < 96) cbuf[w][pos] = code;
            }
            cc += __popc(msk);
        }
    }
    if (cc > 96) cc = 96;
    __syncwarp();

    float best = -3.0e38f;
    int bidx = 1 << 30;
    auto score = [&](int code) {
        const float4* er = (const float4*)(g_Et + (size_t)code * DIM);
        float4 e0 = er[lane], e1 = er[lane + 32];
        float s = z0.x * e0.x + z0.y * e0.y + z0.z * e0.z + z0.w * e0.w
                + z1.x * e1.x + z1.y * e1.y + z1.z * e1.z + z1.w * e1.w;
        #pragma unroll
        for (int off = 16; off; off >>= 1) s += __shfl_xor_sync(0xffffffffu, s, off);
        return s - g_halfnorm[code];
    };
    for (int i = 0; i < cc; i++) {
        int code = cbuf[w][i];
        float sc = score(code);
        if (sc > best || (sc == best && code < bidx)) { best = sc; bidx = code; }
    }
    // phase 3: overflowed slots -> exact scan of that slot's 512 codes
    while (ovf) {
        int s = __ffs(ovf) - 1; ovf &= ovf - 1;
        int nwp = s >> 2, cl = s & 3;
        for (int blk = 0; blk < 64; blk++)
            #pragma unroll
            for (int g = 0; g < 4; g++)
                #pragma unroll
                for (int d = 0; d < 2; d++) {
                    int code = blk * 128 + nwp * 32 + g * 8 + cl * 2 + d;
                    float sc = score(code);
                    if (sc > best || (sc == best && code < bidx)) { best = sc; bidx = code; }
                }
    }
    if (lane == 0) g_ind[row] = bidx;
}

// ---------------------------------------------------------------------------
// Gather quantize rows + diff + segment sums
// ---------------------------------------------------------------------------
__global__ void gather_kernel(const float* __restrict__ z, float* __restrict__ out) {
    int w    = threadIdx.x >> 5;
    int lane = threadIdx.x & 31;
    int row  = blockIdx.x * 8 + w;
    int ind  = g_ind[row];

    const float4* zr = (const float4*)(z + (size_t)row * DIM);
    const float4* qr = (const float4*)(g_Et + (size_t)ind * DIM);
    float4* orow = (float4*)(out + OFF_Q + (size_t)row * DIM);

    float local = 0.0f;
    #pragma unroll
    for (int s = 0; s < 2; s++) {
        int c = lane + s * 32;
        float4 zv = zr[c];
        float4 qv = qr[c];
        float dx = qv.x - zv.x, dy = qv.y - zv.y, dz = qv.z - zv.z, dw = qv.w - zv.w;
        float4 ov;
        ov.x = zv.x + dx; ov.y = zv.y + dy; ov.z = zv.z + dz; ov.w = zv.w + dw;
        orow[c] = ov;
        local += dx * dx + dy * dy + dz * dz + dw * dw;
        int d = c * 4;
        atomicAdd(&g_embed_sum[(size_t)(d + 0) * NEMB + ind], zv.x);
        atomicAdd(&g_embed_sum[(size_t)(d + 1) * NEMB + ind], zv.y);
        atomicAdd(&g_embed_sum[(size_t)(d + 2) * NEMB + ind], zv.z);
        atomicAdd(&g_embed_sum[(size_t)(d + 3) * NEMB + ind], zv.w);
    }
    #pragma unroll
    for (int off = 16; off; off >>= 1) local += __shfl_down_sync(0xffffffffu, local, off);
    if (lane == 0) {
        atomicAdd(&g_scal[0], local);
        atomicAdd(&g_onehot[ind], 1.0f);
        out[OFF_IND + row] = (float)ind;
    }
}

__global__ void cluster_kernel(const float* __restrict__ cs, float* __restrict__ out) {
    int j = blockIdx.x * blockDim.x + threadIdx.x;
    float ncs = cs[j] * DECAYF + OMDEC * g_onehot[j];
    out[OFF_NCS + j] = ncs;
    float s = ncs;
    #pragma unroll
    for (int off = 16; off; off >>= 1) s += __shfl_down_sync(0xffffffffu, s, off);
    __shared__ float red[8];
    int lane = threadIdx.x & 31, w = threadIdx.x >> 5;
    if (lane == 0) red[w] = s;
    __syncthreads();
    if (threadIdx.x == 0) {
        float t = 0.0f;
        #pragma unroll
        for (int i = 0; i < 8; i++) t += red[i];
        atomicAdd(&g_scal[1], t);
    }
}

__global__ void final_kernel(const float* __restrict__ eavg, float* __restrict__ out) {
    size_t idx = (size_t)blockIdx.x * blockDim.x + threadIdx.x;
    int j = (int)(idx & (NEMB - 1));
    float ea = eavg[idx] * DECAYF + OMDEC * g_embed_sum[idx];
    out[OFF_NEA + idx] = ea;
    float n = g_scal[1];
    float ncs = out[OFF_NCS + j];
    float smoothed = (ncs + EPSF) / (n + (float)NEMB * EPSF) * n;
    out[OFF_NE + idx] = ea / smoothed;
    if (idx == 0) out[OFF_DIFF] = g_scal[0] * (1.0f / (float)(NROWS * DIM));
}

// ---------------------------------------------------------------------------
extern "C" void kernel_launch(void* const* d_in, const int* in_sizes, int n_in,
                              void* d_out, int out_size) {
    const float* z    = (const float*)d_in[0];
    const float* emb  = (const float*)d_in[1];
    const float* cs   = (const float*)d_in[2];
    const float* eavg = (const float*)d_in[3];
    float* out = (float*)d_out;

    cudaFuncSetAttribute(imma_argmax_kernel,
                         cudaFuncAttributeMaxDynamicSharedMemorySize, SMEM_TOTAL);

    zero_kernel<<<2048, 256>>>();
    transpose_kernel<<<dim3(NEMB / 32, DIM / 32), dim3(32, 8)>>>(emb);
    convz_kernel<<<(NROWS * DIM / 4) / 256, 256>>>(z);
    norm_kernel<<<NEMB / 8, 256>>>();
    imma_argmax_kernel<<<NROWS / 64, 256, SMEM_TOTAL>>>();
    rescore_kernel<<<NROWS / 8, 256>>>(z);
    gather_kernel<<<NROWS / 8, 256>>>(z, out);
    cluster_kernel<<<NEMB / 256, 256>>>(cs, out);
    final_kernel<<<(DIM * NEMB) / 256, 256>>>(eavg, out);
}

// round 11
// speedup vs baseline: 1.7482x; 1.7482x over previous
#include <cuda_runtime.h>
#include <cuda_bf16.h>
#include <cstdint>

// Problem constants
#define DIM    256
#define NEMB   8192
#define NROWS  16384            // 16*32*32
#define DECAYF 0.99f
#define OMDEC  0.01f
#define EPSF   1e-5f
#define MARGIN 0.6f
#define THRC   0.5f
#define CCAP   32               // candidates per (row, slot)
#define NSLOT  8                // slots per row (2 nwarp x 4 lane%4)

// Output layout (flattened concatenation of reference return tuple, all fp32)
#define OFF_Q    0ul
#define OFF_DIFF 4194304ul
#define OFF_IND  4194305ul
#define OFF_NE   4210689ul
#define OFF_NCS  6307841ul
#define OFF_NEA  6316033ul

// ---------------------------------------------------------------------------
// Device scratch
// ---------------------------------------------------------------------------
__device__ float          g_Et[(size_t)NEMB * DIM];     // embedding transposed fp32
__device__ __nv_bfloat16  g_Bh[(size_t)NEMB * DIM];     // embedding transposed bf16
__device__ __nv_bfloat16  g_Ah[(size_t)NROWS * DIM];    // z rows bf16
__device__ float          g_halfnorm[NEMB];             // 0.5*||e||^2 fp32
__device__ int2           g_cand[(size_t)NROWS * NSLOT * CCAP];  // {code, score}
__device__ int            g_ccnt[(size_t)NROWS * NSLOT];
__device__ float          g_embed_sum[(size_t)DIM * NEMB];
__device__ float          g_onehot[NEMB];
__device__ float          g_scal[2];                    // [0]=diff_sum, [1]=n_sum

// ---------------------------------------------------------------------------
// PTX helpers — base-target instructions only (cp.async / ldmatrix / mma.sync)
// ---------------------------------------------------------------------------
__device__ __forceinline__ uint32_t smem_u32(const void* p) {
    uint32_t a;
    asm("{ .reg .u64 t; cvta.to.shared.u64 t, %1; cvt.u32.u64 %0, t; }" : "=r"(a) : "l"(p));
    return a;
}
#define SW128(x) ((x) ^ (((x) >> 3) & 0x70))
#define CP_ASYNC16(dst, src) \
    asm volatile("cp.async.cg.shared.global [%0], [%1], 16;" :: "r"(dst), "l"(src) : "memory")
#define CP_COMMIT() asm volatile("cp.async.commit_group;" ::: "memory")
#define CP_WAIT0()  asm volatile("cp.async.wait_group 0;" ::: "memory")

#define LDSM4(r, addr) \
    asm volatile("ldmatrix.sync.aligned.m8n8.x4.shared.b16 {%0,%1,%2,%3}, [%4];" \
        : "=r"((r)[0]), "=r"((r)[1]), "=r"((r)[2]), "=r"((r)[3]) : "r"(addr))

#define MMA16816(c, a, b0, b1) \
    asm volatile("mma.sync.aligned.m16n8k16.row.col.f32.bf16.bf16.f32 " \
        "{%0,%1,%2,%3}, {%4,%5,%6,%7}, {%8,%9}, {%0,%1,%2,%3};" \
        : "+f"((c)[0]), "+f"((c)[1]), "+f"((c)[2]), "+f"((c)[3]) \
        : "r"((a)[0]), "r"((a)[1]), "r"((a)[2]), "r"((a)[3]), "r"(b0), "r"(b1))

// ---------------------------------------------------------------------------
// Zero the accumulators
// ---------------------------------------------------------------------------
__global__ void zero_kernel() {
    int i = blockIdx.x * blockDim.x + threadIdx.x;
    int stride = gridDim.x * blockDim.x;
    for (size_t k = i; k < (size_t)DIM * NEMB; k += stride) g_embed_sum[k] = 0.0f;
    if (i < NEMB) g_onehot[i] = 0.0f;
    if (i < 2)    g_scal[i]   = 0.0f;
}

// ---------------------------------------------------------------------------
// Transpose embedding [DIM, NEMB] -> Et [NEMB, DIM] fp32 + bf16
// ---------------------------------------------------------------------------
__global__ void transpose_kernel(const float* __restrict__ E) {
    __shared__ float tile[32][33];
    int jx = blockIdx.x * 32;
    int dy = blockIdx.y * 32;
    int tx = threadIdx.x;
    #pragma unroll
    for (int r = threadIdx.y; r < 32; r += 8)
        tile[r][tx] = E[(size_t)(dy + r) * NEMB + jx + tx];
    __syncthreads();
    #pragma unroll
    for (int r = threadIdx.y; r < 32; r += 8) {
        float v = tile[tx][r];
        size_t o = (size_t)(jx + r) * DIM + dy + tx;
        g_Et[o] = v;
        g_Bh[o] = __float2bfloat16(v);
    }
}

// ---------------------------------------------------------------------------
// z -> bf16
// ---------------------------------------------------------------------------
__global__ void convz_kernel(const float* __restrict__ z) {
    size_t i = (size_t)blockIdx.x * blockDim.x + threadIdx.x;   // one float4
    float4 v = ((const float4*)z)[i];
    __nv_bfloat16* o = g_Ah + i * 4;
    o[0] = __float2bfloat16(v.x); o[1] = __float2bfloat16(v.y);
    o[2] = __float2bfloat16(v.z); o[3] = __float2bfloat16(v.w);
}

// ---------------------------------------------------------------------------
// halfnorm
// ---------------------------------------------------------------------------
__global__ void norm_kernel() {
    int w    = threadIdx.x >> 5;
    int lane = threadIdx.x & 31;
    int j = blockIdx.x * 8 + w;
    const float4* e4 = (const float4*)(g_Et + (size_t)j * DIM);
    float s = 0.0f;
    float4 v = e4[lane];
    s += v.x * v.x + v.y * v.y + v.z * v.z + v.w * v.w;
    v = e4[lane + 32];
    s += v.x * v.x + v.y * v.y + v.z * v.z + v.w * v.w;
    #pragma unroll
    for (int off = 16; off; off >>= 1) s += __shfl_down_sync(0xffffffffu, s, off);
    if (lane == 0) g_halfnorm[j] = 0.5f * s;
}

// ---------------------------------------------------------------------------
// HMMA (mma.sync bf16) distance GEMM + margin-candidate argmax
// (identical structure to the 481.7us build; candidates now carry scores).
// 256 threads = 8 warps: warp w -> mwarp = w&3 (rows), nwarp = w>>2 (cols).
// Tile M=128, N=128/tile, K=256 (A resident in smem, B double-buffered).
// ---------------------------------------------------------------------------
#define SMEM_A      0
#define SMEM_B0     65536
#define SMEM_B1     131072
#define SMEM_TOTAL  196608

__global__ void __launch_bounds__(256, 1)
hmma_argmax_kernel() {
    extern __shared__ __align__(1024) char smem[];
    uint32_t sb = smem_u32(smem);
    const int tid = threadIdx.x, wid = tid >> 5, lane = tid & 31;
    const int mwarp = wid & 3, nwarp = wid >> 2;
    const int m0 = blockIdx.x * 128;

    // ---- prologue: A tile + B tile 0 ----
    {
        const __nv_bfloat16* Arow = g_Ah + (size_t)m0 * DIM;
        for (int u = tid; u < 4096; u += 256) {
            int chunk = u >> 10, rem = u & 1023, row = rem >> 3, seg = rem & 7;
            uint32_t dst = sb + SMEM_A + chunk * 16384 + SW128(row * 128 + seg * 16);
            CP_ASYNC16(dst, Arow + (size_t)row * DIM + chunk * 64 + seg * 8);
        }
        for (int u = tid; u < 4096; u += 256) {
            int chunk = u >> 10, rem = u & 1023, row = rem >> 3, seg = rem & 7;
            uint32_t dst = sb + SMEM_B0 + chunk * 16384 + SW128(row * 128 + seg * 16);
            CP_ASYNC16(dst, g_Bh + (size_t)row * DIM + chunk * 64 + seg * 8);
        }
        CP_COMMIT(); CP_WAIT0();
    }
    __syncthreads();

    // per-thread row ownership (c-frag layout): rows q, q+8 within each m16
    const int q = lane >> 2;
    int rowIdx[4];
    rowIdx[0] = m0 + mwarp * 32 + q;
    rowIdx[1] = rowIdx[0] + 8;
    rowIdx[2] = rowIdx[0] + 16;
    rowIdx[3] = rowIdx[0] + 24;
    const int slot = nwarp * 4 + (lane & 3);
    const int colb = (lane & 3) * 2;

    float best[4] = {-3.0e38f, -3.0e38f, -3.0e38f, -3.0e38f};
    int   cnt[4]  = {0, 0, 0, 0};

    const int alr = lane & 15;          // row within m16
    const int kseg16 = (lane >> 4) * 16;

    for (int t = 0; t < 64; t++) {
        const uint32_t bbase = sb + ((t & 1) ? SMEM_B1 : SMEM_B0);

        // prefetch next B tile into the other buffer
        if (t + 1 < 64) {
            uint32_t nb = sb + (((t + 1) & 1) ? SMEM_B1 : SMEM_B0);
            const __nv_bfloat16* Brow = g_Bh + (size_t)(t + 1) * 128 * DIM;
            for (int u = tid; u < 4096; u += 256) {
                int chunk = u >> 10, rem = u & 1023, row = rem >> 3, seg = rem & 7;
                CP_ASYNC16(nb + chunk * 16384 + SW128(row * 128 + seg * 16),
                           Brow + (size_t)row * DIM + chunk * 64 + seg * 8);
            }
            CP_COMMIT();
        }

        float acc[2][8][4];
        #pragma unroll
        for (int m = 0; m < 2; m++)
            #pragma unroll
            for (int nb = 0; nb < 8; nb++)
                #pragma unroll
                for (int r = 0; r < 4; r++) acc[m][nb][r] = 0.0f;

        #pragma unroll 4
        for (int ks = 0; ks < 16; ks++) {
            const int kchunk = ks >> 2;
            const int koff = (ks & 3) * 32 + kseg16;
            const uint32_t chbase = kchunk * 16384;

            uint32_t aF[2][4];
            LDSM4(aF[0], sb + SMEM_A + chbase + SW128((mwarp * 32 + alr) * 128 + koff));
            LDSM4(aF[1], sb + SMEM_A + chbase + SW128((mwarp * 32 + 16 + alr) * 128 + koff));

            uint32_t bF[4][4];
            #pragma unroll
            for (int p = 0; p < 4; p++)
                LDSM4(bF[p], bbase + chbase + SW128((nwarp * 64 + p * 16 + alr) * 128 + koff));

            #pragma unroll
            for (int m = 0; m < 2; m++)
                #pragma unroll
                for (int p = 0; p < 4; p++) {
                    MMA16816(acc[m][2 * p],     aF[m], bF[p][0], bF[p][2]);
                    MMA16816(acc[m][2 * p + 1], aF[m], bF[p][1], bF[p][3]);
                }
        }

        // ---- epilogue: scores -> margin candidates (carry approx score) ----
        const int n0 = t * 128 + nwarp * 64;
        #pragma unroll
        for (int nb = 0; nb < 8; nb++) {
            const int c0 = n0 + nb * 8 + colb;
            const float hn0 = __ldg(&g_halfnorm[c0]);
            const float hn1 = __ldg(&g_halfnorm[c0 + 1]);
            #pragma unroll
            for (int m = 0; m < 2; m++) {
                float s00 = acc[m][nb][0] - hn0;   // row q,   col c0
                float s01 = acc[m][nb][1] - hn1;   // row q,   col c0+1
                float s10 = acc[m][nb][2] - hn0;   // row q+8, col c0
                float s11 = acc[m][nb][3] - hn1;   // row q+8, col c0+1
                const int r0 = m * 2, r1 = m * 2 + 1;
                if (s00 > best[r0] - MARGIN) {
                    if (cnt[r0] < CCAP)
                        g_cand[((size_t)rowIdx[r0] * NSLOT + slot) * CCAP + cnt[r0]]
                            = make_int2(c0, __float_as_int(s00));
                    cnt[r0]++; if (s00 > best[r0]) best[r0] = s00;
                }
                if (s01 > best[r0] - MARGIN) {
                    if (cnt[r0] < CCAP)
                        g_cand[((size_t)rowIdx[r0] * NSLOT + slot) * CCAP + cnt[r0]]
                            = make_int2(c0 + 1, __float_as_int(s01));
                    cnt[r0]++; if (s01 > best[r0]) best[r0] = s01;
                }
                if (s10 > best[r1] - MARGIN) {
                    if (cnt[r1] < CCAP)
                        g_cand[((size_t)rowIdx[r1] * NSLOT + slot) * CCAP + cnt[r1]]
                            = make_int2(c0, __float_as_int(s10));
                    cnt[r1]++; if (s10 > best[r1]) best[r1] = s10;
                }
                if (s11 > best[r1] - MARGIN) {
                    if (cnt[r1] < CCAP)
                        g_cand[((size_t)rowIdx[r1] * NSLOT + slot) * CCAP + cnt[r1]]
                            = make_int2(c0 + 1, __float_as_int(s11));
                    cnt[r1]++; if (s11 > best[r1]) best[r1] = s11;
                }
            }
        }

        if (t + 1 < 64) CP_WAIT0();
        __syncthreads();
    }

    #pragma unroll
    for (int r = 0; r < 4; r++)
        g_ccnt[(size_t)rowIdx[r] * NSLOT + slot] = cnt[r];
}

// ---------------------------------------------------------------------------
// Merged finalize: contender-only fp32 rescore -> exact argmin, then gather
// quantize row + diff + segment-sum atomics. One warp per row.
// ---------------------------------------------------------------------------
__global__ void finalize_kernel(const float* __restrict__ z, float* __restrict__ out) {
    __shared__ int cbuf[8][96];
    int w = threadIdx.x >> 5, lane = threadIdx.x & 31;
    int row = blockIdx.x * 8 + w;
    const float4* zr = (const float4*)(z + (size_t)row * DIM);
    float4 z0 = zr[lane], z1 = zr[lane + 32];

    int cnt_s = (lane < NSLOT) ? g_ccnt[(size_t)row * NSLOT + lane] : 0;
    unsigned ovf = __ballot_sync(0xffffffffu, lane < NSLOT && cnt_s > CCAP);

    // phase 1: approx max over stored candidate scores
    float am = -3.0e38f;
    for (int s = 0; s < NSLOT; s++) {
        int n = min(__shfl_sync(0xffffffffu, cnt_s, s), CCAP);
        const int2* lst = g_cand + ((size_t)row * NSLOT + s) * CCAP;
        for (int e = lane; e < n; e += 32)
            am = fmaxf(am, __int_as_float(lst[e].y));
    }
    #pragma unroll
    for (int off = 16; off; off >>= 1)
        am = fmaxf(am, __shfl_xor_sync(0xffffffffu, am, off));

    // phase 2: gather contenders (approx score within THRC of approx max)
    int cc = 0;
    for (int s = 0; s < NSLOT; s++) {
        int n = min(__shfl_sync(0xffffffffu, cnt_s, s), CCAP);
        const int2* lst = g_cand + ((size_t)row * NSLOT + s) * CCAP;
        for (int base = 0; base < n; base += 32) {
            int e = base + lane;
            bool hit = false; int code = 0;
            if (e < n) {
                int2 v = lst[e];
                if (__int_as_float(v.y) >= am - THRC) { hit = true; code = v.x; }
            }
            unsigned msk = __ballot_sync(0xffffffffu, hit);
            if (hit) {
                int pos = cc + __popc(msk & ((1u << lane) - 1u));
                if (pos < 96) cbuf[w][pos] = code;
            }
            cc += __popc(msk);
        }
    }
    __syncwarp();

    float best = -3.0e38f;
    int bidx = 1 << 30;
    auto score = [&](int code) {
        const float4* er = (const float4*)(g_Et + (size_t)code * DIM);
        float4 e0 = er[lane], e1 = er[lane + 32];
        float s = z0.x * e0.x + z0.y * e0.y + z0.z * e0.z + z0.w * e0.w
                + z1.x * e1.x + z1.y * e1.y + z1.z * e1.z + z1.w * e1.w;
        #pragma unroll
        for (int off = 16; off; off >>= 1) s += __shfl_xor_sync(0xffffffffu, s, off);
        return s - g_halfnorm[code];
    };

    if (cc <= 96) {
        for (int i = 0; i < cc; i++) {
            int code = cbuf[w][i];
            float sc = score(code);
            if (sc > best || (sc == best && code < bidx)) { best = sc; bidx = code; }
        }
    } else {
        // pathological: exact-score every stored candidate
        for (int s = 0; s < NSLOT; s++) {
            int n = min(__shfl_sync(0xffffffffu, cnt_s, s), CCAP);
            const int2* lst = g_cand + ((size_t)row * NSLOT + s) * CCAP;
            for (int i = 0; i < n; i++) {
                int code = lst[i].x;
                float sc = score(code);
                if (sc > best || (sc == best && code < bidx)) { best = sc; bidx = code; }
            }
        }
    }
    // phase 3: overflowed slots -> exact scan of that slot's 1024 codes
    while (ovf) {
        int s = __ffs(ovf) - 1; ovf &= ovf - 1;
        int nwp = s >> 2, cl = s & 3;
        for (int blk = 0; blk < 64; blk++)
            #pragma unroll
            for (int nb = 0; nb < 8; nb++)
                #pragma unroll
                for (int d = 0; d < 2; d++) {
                    int code = blk * 128 + nwp * 64 + nb * 8 + cl * 2 + d;
                    float sc = score(code);
                    if (sc > best || (sc == best && code < bidx)) { best = sc; bidx = code; }
                }
    }

    // ---- gather / quantize / diff / segment sums ----
    const int ind = bidx;
    const float4* qr = (const float4*)(g_Et + (size_t)ind * DIM);
    float4* orow = (float4*)(out + OFF_Q + (size_t)row * DIM);
    float local = 0.0f;
    #pragma unroll
    for (int s = 0; s < 2; s++) {
        int c = lane + s * 32;
        float4 zv = (s == 0) ? z0 : z1;
        float4 qv = qr[c];
        float dx = qv.x - zv.x, dy = qv.y - zv.y, dz = qv.z - zv.z, dw = qv.w - zv.w;
        float4 ov;
        ov.x = zv.x + dx; ov.y = zv.y + dy; ov.z = zv.z + dz; ov.w = zv.w + dw;
        orow[c] = ov;
        local += dx * dx + dy * dy + dz * dz + dw * dw;
        int d = c * 4;
        atomicAdd(&g_embed_sum[(size_t)(d + 0) * NEMB + ind], zv.x);
        atomicAdd(&g_embed_sum[(size_t)(d + 1) * NEMB + ind], zv.y);
        atomicAdd(&g_embed_sum[(size_t)(d + 2) * NEMB + ind], zv.z);
        atomicAdd(&g_embed_sum[(size_t)(d + 3) * NEMB + ind], zv.w);
    }
    #pragma unroll
    for (int off = 16; off; off >>= 1) local += __shfl_down_sync(0xffffffffu, local, off);
    if (lane == 0) {
        atomicAdd(&g_scal[0], local);
        atomicAdd(&g_onehot[ind], 1.0f);
        out[OFF_IND + row] = (float)ind;
    }
}

__global__ void cluster_kernel(const float* __restrict__ cs, float* __restrict__ out) {
    int j = blockIdx.x * blockDim.x + threadIdx.x;
    float ncs = cs[j] * DECAYF + OMDEC * g_onehot[j];
    out[OFF_NCS + j] = ncs;
    float s = ncs;
    #pragma unroll
    for (int off = 16; off; off >>= 1) s += __shfl_down_sync(0xffffffffu, s, off);
    __shared__ float red[8];
    int lane = threadIdx.x & 31, w = threadIdx.x >> 5;
    if (lane == 0) red[w] = s;
    __syncthreads();
    if (threadIdx.x == 0) {
        float t = 0.0f;
        #pragma unroll
        for (int i = 0; i < 8; i++) t += red[i];
        atomicAdd(&g_scal[1], t);
    }
}

__global__ void final_kernel(const float* __restrict__ eavg, float* __restrict__ out) {
    size_t idx = (size_t)blockIdx.x * blockDim.x + threadIdx.x;
    int j = (int)(idx & (NEMB - 1));
    float ea = eavg[idx] * DECAYF + OMDEC * g_embed_sum[idx];
    out[OFF_NEA + idx] = ea;
    float n = g_scal[1];
    float ncs = out[OFF_NCS + j];
    float smoothed = (ncs + EPSF) / (n + (float)NEMB * EPSF) * n;
    out[OFF_NE + idx] = ea / smoothed;
    if (idx == 0) out[OFF_DIFF] = g_scal[0] * (1.0f / (float)(NROWS * DIM));
}

// ---------------------------------------------------------------------------
extern "C" void kernel_launch(void* const* d_in, const int* in_sizes, int n_in,
                              void* d_out, int out_size) {
    const float* z    = (const float*)d_in[0];
    const float* emb  = (const float*)d_in[1];
    const float* cs   = (const float*)d_in[2];
    const float* eavg = (const float*)d_in[3];
    float* out = (float*)d_out;

    cudaFuncSetAttribute(hmma_argmax_kernel,
                         cudaFuncAttributeMaxDynamicSharedMemorySize, SMEM_TOTAL);

    zero_kernel<<<2048, 256>>>();
    transpose_kernel<<<dim3(NEMB / 32, DIM / 32), dim3(32, 8)>>>(emb);
    convz_kernel<<<(NROWS * DIM / 4) / 256, 256>>>(z);
    norm_kernel<<<NEMB / 8, 256>>>();
    hmma_argmax_kernel<<<NROWS / 128, 256, SMEM_TOTAL>>>();
    finalize_kernel<<<NROWS / 8, 256>>>(z, out);
    cluster_kernel<<<NEMB / 256, 256>>>(cs, out);
    final_kernel<<<(DIM * NEMB) / 256, 256>>>(eavg, out);
}